// round 5
// baseline (speedup 1.0000x reference)
#include <cuda_runtime.h>
#include <cstdint>

#define B 8
#define N 100000
#define V 40
#define NBINS 64000
#define NTILES 63                    // ceil(64000/1024)
#define PB_F4 1296000                // float4s per batch (V^3*81/4)
#define TOT_F4 (B * PB_F4)           // 10,368,000

// Output layout (float32 elements)
#define O_IDX  0
#define O_HASH 800000
#define O_NBR  1600000
#define O_MASK 43072000

// ---- scratch ----
__device__ int g_voxel[B * N];
__device__ int g_hist[B * NBINS];        // counts -> offsets; re-zeroed by finalize
__device__ int g_cursor[B * NBINS];
__device__ int g_sorted[B * N];
__device__ unsigned g_state[B * NTILES]; // lookback state; re-zeroed by bin_kernel

#define FLAG_AGG (1u << 30)
#define FLAG_PRE (2u << 30)
#define VAL_MASK ((1u << 30) - 1u)

// ---------------------------------------------------------------------------
// bin: 4 points/thread via float4 loads; also resets g_state for the scan.
__global__ void bin_kernel(const float* __restrict__ pts) {
    int gi = blockIdx.x * blockDim.x + threadIdx.x;
    if (gi < B * NTILES) g_state[gi] = 0u;     // replay-safe reset (scan runs later)
    if (gi >= (B * N) / 4) return;
    const float4* p4 = (const float4*)pts;
    float4 f0 = __ldg(&p4[3 * gi]);
    float4 f1 = __ldg(&p4[3 * gi + 1]);
    float4 f2 = __ldg(&p4[3 * gi + 2]);
    int b = gi / (N / 4);
    float px[4] = { f0.x, f0.w, f1.z, f2.y };
    float py[4] = { f0.y, f1.x, f1.w, f2.z };
    float pz[4] = { f0.z, f1.y, f2.x, f2.w };
    int bins[4];
    #pragma unroll
    for (int k = 0; k < 4; k++) {
        int cx = (int)(px[k] * (float)(V - 1));
        int cy = (int)(py[k] * (float)(V - 1));
        int cz = (int)(pz[k] * (float)(V - 1));
        bins[k] = cx * (V * V) + cy * V + cz;
    }
    *(int4*)(g_voxel + 4 * gi) = make_int4(bins[0], bins[1], bins[2], bins[3]);
    #pragma unroll
    for (int k = 0; k < 4; k++) atomicAdd(&g_hist[b * NBINS + bins[k]], 1);
}

// ---------------------------------------------------------------------------
// Single-pass decoupled-lookback scan. One block per (batch, tile of 1024 bins).
__global__ void scan_kernel() {
    int b = blockIdx.x / NTILES;
    int t = blockIdx.x - b * NTILES;
    int tid = threadIdx.x;
    int tb = t * 1024 + tid * 4;

    int4 v = make_int4(0, 0, 0, 0);
    if (tb < NBINS) v = *(const int4*)(g_hist + b * NBINS + tb);
    int tsum = v.x + v.y + v.z + v.w;

    // block-wide inclusive scan of thread sums
    int lane = tid & 31, warp = tid >> 5;
    int x = tsum;
    #pragma unroll
    for (int o = 1; o < 32; o <<= 1) {
        int tt = __shfl_up_sync(0xFFFFFFFFu, x, o);
        if (lane >= o) x += tt;
    }
    __shared__ int ws[8];
    __shared__ int s_excl;
    if (lane == 31) ws[warp] = x;
    __syncthreads();
    int woff = 0, total = 0;
    #pragma unroll
    for (int w = 0; w < 8; w++) {
        int wv = ws[w];
        woff += (w < warp) ? wv : 0;
        total += wv;
    }

    if (tid == 0) {
        volatile unsigned* st = g_state + b * NTILES;
        if (t == 0) {
            __threadfence();
            st[0] = (unsigned)total | FLAG_PRE;
            s_excl = 0;
        } else {
            __threadfence();
            st[t] = (unsigned)total | FLAG_AGG;      // publish aggregate early
            int excl = 0;
            for (int j = t - 1; j >= 0; ) {
                unsigned s;
                do { s = st[j]; } while (!(s >> 30));
                excl += (int)(s & VAL_MASK);
                if ((s >> 30) == 2u) break;          // PREFIX: done
                j--;
            }
            __threadfence();
            st[t] = (unsigned)(excl + total) | FLAG_PRE;
            s_excl = excl;
        }
    }
    __syncthreads();

    int base = s_excl + woff + x - tsum;
    if (tb < NBINS) {
        int4 o4;
        o4.x = base;
        o4.y = base + v.x;
        o4.z = base + v.x + v.y;
        o4.w = base + v.x + v.y + v.z;
        *(int4*)(g_hist + b * NBINS + tb) = o4;
        *(int4*)(g_cursor + b * NBINS + tb) = o4;
    }
}

// ---------------------------------------------------------------------------
// scatter: 4 points/thread, int4 voxel load, 4 independent atomics in flight.
__global__ void scatter_kernel() {
    int gi = blockIdx.x * blockDim.x + threadIdx.x;
    if (gi >= (B * N) / 4) return;
    int i0 = gi * 4;
    int b = gi / (N / 4);
    int4 vb = *(const int4*)(g_voxel + i0);
    int bins[4] = { vb.x, vb.y, vb.z, vb.w };
    int pos[4];
    #pragma unroll
    for (int k = 0; k < 4; k++)
        pos[k] = atomicAdd(&g_cursor[b * NBINS + bins[k]], 1);
    int nbase = i0 - b * N;
    #pragma unroll
    for (int k = 0; k < 4; k++)
        g_sorted[b * N + pos[k]] = nbase + k;
}

// ---------------------------------------------------------------------------
// finalize: stable fixup + idx/hash/mask; restores g_hist zeros for replay.
__global__ void finalize_kernel(float* __restrict__ out) {
    int t = blockIdx.x * blockDim.x + threadIdx.x;
    if (t >= B * NBINS) return;
    int b = t / NBINS;
    int bin = t - b * NBINS;
    int s = g_hist[b * NBINS + bin];
    int e = g_cursor[b * NBINS + bin];       // post-scatter cursor == segment end
    g_hist[b * NBINS + bin] = 0;
    int* seg = g_sorted + b * N;

    for (int a = s + 1; a < e; a++) {        // tiny segments (Poisson mean ~1.6)
        int key = seg[a];
        int j = a - 1;
        while (j >= s && seg[j] > key) { seg[j + 1] = seg[j]; j--; }
        seg[j + 1] = key;
    }

    int cx = bin / (V * V);
    int cy = (bin / V) % V;
    int cz = bin % V;
    float h = (float)(cx * 10000 + cy * 100 + cz);
    for (int j = s; j < e; j++) {
        out[O_IDX  + b * N + j] = (float)seg[j];
        out[O_HASH + b * N + j] = h;
    }
    out[O_MASK + b * NBINS + bin] = (e > s && e < N) ? 1.0f : 0.0f;
}

// ---------------------------------------------------------------------------
// neighbour table: one thread writes 4 consecutive float4s (64B) — a single
// sequential streaming-write pattern over the whole 166MB range.
__global__ void neighbour_kernel(float* __restrict__ out) {
    __shared__ int   s_sel[81];
    __shared__ float s_add[81];
    if (threadIdx.x < 81) {
        int j = threadIdx.x;
        int c = j % 3, m = j / 3;
        int d = (c == 0) ? (m / 9 - 1) : (c == 1) ? ((m / 3) % 3 - 1) : (m % 3 - 1);
        s_sel[j] = c;
        s_add[j] = (float)d;
    }
    __syncthreads();

    int gi = blockIdx.x * blockDim.x + threadIdx.x;
    if (gi >= TOT_F4 / 4) return;
    int f0 = gi * 4;                      // first float4 index (global)
    int b  = f0 / PB_F4;                  // constant across the 4 (PB_F4 % 4 == 0)
    int q0 = f0 - b * PB_F4;
    float4* pout = (float4*)(out + O_NBR) + (size_t)b * PB_F4 + q0;

    #pragma unroll
    for (int k = 0; k < 4; k++) {
        int e0  = (q0 + k) * 4;
        int vox = e0 / 81;
        int j0  = e0 - vox * 81;
        int x = vox / (V * V);
        int r = vox - x * (V * V);
        int y = r / V;
        int z = r - y * V;
        int zn = z + 1, yn = y, xn = x;
        if (zn == V) { zn = 0; yn = y + 1; if (yn == V) { yn = 0; xn = x + 1; } }
        float c0[3] = { (float)x,  (float)y,  (float)z  };
        float c1[3] = { (float)xn, (float)yn, (float)zn };
        float4 vv;
        float* vp = &vv.x;
        #pragma unroll
        for (int u = 0; u < 4; u++) {
            int jk = j0 + u;
            bool w = jk >= 81;
            int jj = w ? jk - 81 : jk;
            vp[u] = (w ? c1[s_sel[jj]] : c0[s_sel[jj]]) + s_add[jj];
        }
        __stcs(&pout[k], vv);
    }
}

// ---------------------------------------------------------------------------
extern "C" void kernel_launch(void* const* d_in, const int* in_sizes, int n_in,
                              void* d_out, int out_size) {
    const float* pts = (const float*)d_in[0];
    float* out = (float*)d_out;

    static cudaStream_t sA = nullptr, sB = nullptr;
    static cudaEvent_t evF = nullptr, evA = nullptr, evB = nullptr;
    if (sA == nullptr) {
        cudaStreamCreateWithFlags(&sA, cudaStreamNonBlocking);
        cudaStreamCreateWithFlags(&sB, cudaStreamNonBlocking);
        cudaEventCreateWithFlags(&evF, cudaEventDisableTiming);
        cudaEventCreateWithFlags(&evA, cudaEventDisableTiming);
        cudaEventCreateWithFlags(&evB, cudaEventDisableTiming);
    }

    // fork from legacy stream
    cudaEventRecord(evF, 0);
    cudaStreamWaitEvent(sA, evF, 0);
    cudaStreamWaitEvent(sB, evF, 0);

    // branch B: neighbour table (store-BW bound)
    neighbour_kernel<<<(TOT_F4 / 4 + 255) / 256, 256, 0, sB>>>(out);
    cudaEventRecord(evB, sB);

    // branch A: sort chain (latency bound)
    bin_kernel     <<<(B * N / 4 + 255) / 256, 256, 0, sA>>>(pts);
    scan_kernel    <<<B * NTILES,            256, 0, sA>>>();
    scatter_kernel <<<(B * N / 4 + 255) / 256, 256, 0, sA>>>();
    finalize_kernel<<<(B * NBINS + 255) / 256, 256, 0, sA>>>(out);
    cudaEventRecord(evA, sA);

    // join to legacy stream
    cudaStreamWaitEvent(0, evA, 0);
    cudaStreamWaitEvent(0, evB, 0);
}

// round 6
// speedup vs baseline: 1.4321x; 1.4321x over previous
#include <cuda_runtime.h>
#include <cstdint>

#define B 8
#define N 100000
#define V 40
#define NBINS 64000
#define NTILES 63                    // ceil(64000/1024)
#define PB_F  5184000                // floats per batch in nbr table (V^3*81)

// Output layout (float32 elements)
#define O_IDX  0
#define O_HASH 800000
#define O_NBR  1600000
#define O_MASK 43072000

// nbr chunking: 2 y-rows per block = 80 voxels = 6480 floats = 25920 bytes
#define CHUNK_VOX 80
#define CHUNK_F   6480
#define CHUNK_F4  1620
#define CHUNK_BYTES 25920
#define NBR_BLOCKS 800               // V * (V / 2)

// ---- scratch ----
__device__ int g_voxel[B * N];
__device__ int g_hist[B * NBINS];    // counts -> offsets; re-zeroed by finalize
__device__ int g_cursor[B * NBINS];
__device__ int g_sorted[B * N];
__device__ int g_tsum[B * NTILES];

// ---------------------------------------------------------------------------
__device__ __forceinline__ uint32_t smem_u32(const void* p) {
    uint32_t a;
    asm("{ .reg .u64 t; cvta.to.shared.u64 t, %1; cvt.u32.u64 %0, t; }"
        : "=r"(a) : "l"(p));
    return a;
}

// ---------------------------------------------------------------------------
// bin: 4 points/thread via float4 loads.
__global__ void bin_kernel(const float* __restrict__ pts) {
    int gi = blockIdx.x * blockDim.x + threadIdx.x;
    if (gi >= (B * N) / 4) return;
    const float4* p4 = (const float4*)pts;
    float4 f0 = __ldg(&p4[3 * gi]);
    float4 f1 = __ldg(&p4[3 * gi + 1]);
    float4 f2 = __ldg(&p4[3 * gi + 2]);
    int b = gi / (N / 4);
    float px[4] = { f0.x, f0.w, f1.z, f2.y };
    float py[4] = { f0.y, f1.x, f1.w, f2.z };
    float pz[4] = { f0.z, f1.y, f2.x, f2.w };
    int bins[4];
    #pragma unroll
    for (int k = 0; k < 4; k++) {
        int cx = (int)(px[k] * (float)(V - 1));
        int cy = (int)(py[k] * (float)(V - 1));
        int cz = (int)(pz[k] * (float)(V - 1));
        bins[k] = cx * (V * V) + cy * V + cz;
    }
    *(int4*)(g_voxel + 4 * gi) = make_int4(bins[0], bins[1], bins[2], bins[3]);
    #pragma unroll
    for (int k = 0; k < 4; k++) atomicAdd(&g_hist[b * NBINS + bins[k]], 1);
}

// ---- 3-phase scan (proven under concurrency; no spin-waits) ---------------
__global__ void scanA_kernel() {
    int b = blockIdx.x / NTILES;
    int t = blockIdx.x % NTILES;
    int tb = t * 1024 + threadIdx.x * 4;
    int s = 0;
    if (tb < NBINS) {
        int4 v = *(const int4*)(g_hist + b * NBINS + tb);
        s = v.x + v.y + v.z + v.w;
    }
    #pragma unroll
    for (int o = 16; o > 0; o >>= 1) s += __shfl_down_sync(0xFFFFFFFFu, s, o);
    __shared__ int ws[8];
    int lane = threadIdx.x & 31, warp = threadIdx.x >> 5;
    if (lane == 0) ws[warp] = s;
    __syncthreads();
    if (threadIdx.x == 0) {
        int tot = 0;
        #pragma unroll
        for (int w = 0; w < 8; w++) tot += ws[w];
        g_tsum[blockIdx.x] = tot;
    }
}

__global__ void scanB_kernel() {
    int w = threadIdx.x >> 5, lane = threadIdx.x & 31;
    if (w >= B) return;
    int* ts = g_tsum + w * NTILES;
    int v0 = ts[lane];
    int v1 = (lane < NTILES - 32) ? ts[32 + lane] : 0;
    int s0 = v0, s1 = v1;
    #pragma unroll
    for (int o = 1; o < 32; o <<= 1) {
        int t0 = __shfl_up_sync(0xFFFFFFFFu, s0, o);
        int t1 = __shfl_up_sync(0xFFFFFFFFu, s1, o);
        if (lane >= o) { s0 += t0; s1 += t1; }
    }
    int tot0 = __shfl_sync(0xFFFFFFFFu, s0, 31);
    ts[lane] = s0 - v0;
    if (lane < NTILES - 32) ts[32 + lane] = tot0 + s1 - v1;
}

__global__ void scanC_kernel() {
    int b = blockIdx.x / NTILES;
    int t = blockIdx.x % NTILES;
    int tb = t * 1024 + threadIdx.x * 4;
    int4 v = make_int4(0, 0, 0, 0);
    if (tb < NBINS) v = *(const int4*)(g_hist + b * NBINS + tb);
    int tsum = v.x + v.y + v.z + v.w;
    int lane = threadIdx.x & 31, warp = threadIdx.x >> 5;
    int x = tsum;
    #pragma unroll
    for (int o = 1; o < 32; o <<= 1) {
        int tt = __shfl_up_sync(0xFFFFFFFFu, x, o);
        if (lane >= o) x += tt;
    }
    __shared__ int ws[8];
    if (lane == 31) ws[warp] = x;
    __syncthreads();
    int woff = 0;
    #pragma unroll
    for (int w = 0; w < 8; w++) woff += (w < warp) ? ws[w] : 0;
    int base = g_tsum[blockIdx.x] + woff + x - tsum;
    if (tb < NBINS) {
        int4 o4;
        o4.x = base;
        o4.y = base + v.x;
        o4.z = base + v.x + v.y;
        o4.w = base + v.x + v.y + v.z;
        *(int4*)(g_hist + b * NBINS + tb) = o4;
        *(int4*)(g_cursor + b * NBINS + tb) = o4;
    }
}

// scatter: 4 points/thread, 4 independent atomics in flight.
__global__ void scatter_kernel() {
    int gi = blockIdx.x * blockDim.x + threadIdx.x;
    if (gi >= (B * N) / 4) return;
    int i0 = gi * 4;
    int b = gi / (N / 4);
    int4 vb = *(const int4*)(g_voxel + i0);
    int bins[4] = { vb.x, vb.y, vb.z, vb.w };
    int pos[4];
    #pragma unroll
    for (int k = 0; k < 4; k++)
        pos[k] = atomicAdd(&g_cursor[b * NBINS + bins[k]], 1);
    int nbase = i0 - b * N;
    #pragma unroll
    for (int k = 0; k < 4; k++)
        g_sorted[b * N + pos[k]] = nbase + k;
}

// finalize: stable fixup + idx/hash/mask; restores g_hist zeros for replay.
__global__ void finalize_kernel(float* __restrict__ out) {
    int t = blockIdx.x * blockDim.x + threadIdx.x;
    if (t >= B * NBINS) return;
    int b = t / NBINS;
    int bin = t - b * NBINS;
    int s = g_hist[b * NBINS + bin];
    int e = g_cursor[b * NBINS + bin];       // cursor after scatter == segment end
    g_hist[b * NBINS + bin] = 0;
    int* seg = g_sorted + b * N;

    for (int a = s + 1; a < e; a++) {        // tiny segments (Poisson mean ~1.6)
        int key = seg[a];
        int j = a - 1;
        while (j >= s && seg[j] > key) { seg[j + 1] = seg[j]; j--; }
        seg[j + 1] = key;
    }

    int cx = bin / (V * V);
    int cy = (bin / V) % V;
    int cz = bin % V;
    float h = (float)(cx * 10000 + cy * 100 + cz);
    for (int j = s; j < e; j++) {
        out[O_IDX  + b * N + j] = (float)seg[j];
        out[O_HASH + b * N + j] = h;
    }
    out[O_MASK + b * NBINS + bin] = (e > s && e < N) ? 1.0f : 0.0f;
}

// ---------------------------------------------------------------------------
// neighbour table via TMA bulk stores: generate one 25.9KB batch-invariant
// chunk in SMEM, then cp.async.bulk it to all 8 batch copies. Bypasses the
// STG.128 issue-cost floor (~1.6 TB/s) that capped earlier rounds.
__global__ void __launch_bounds__(256) neighbour_kernel(float* __restrict__ out) {
    __shared__ __align__(16) float s_buf[CHUNK_F];
    __shared__ int   s_sel[81];
    __shared__ float s_add[81];

    if (threadIdx.x < 81) {
        int j = threadIdx.x;
        int c = j % 3, m = j / 3;
        int d = (c == 0) ? (m / 9 - 1) : (c == 1) ? ((m / 3) % 3 - 1) : (m % 3 - 1);
        s_sel[j] = c;
        s_add[j] = (float)d;
    }
    __syncthreads();

    int blk = blockIdx.x;                 // 0..799
    int x  = blk / (V / 2);
    int y0 = (blk % (V / 2)) * 2;
    int vox0 = x * (V * V) + y0 * V;      // first voxel of chunk (80 voxels)
    int f0   = vox0 * 81;                 // first float of chunk within a batch

    // generate chunk in SMEM (float4 granularity; chunk is float4-aligned)
    for (int ql = threadIdx.x; ql < CHUNK_F4; ql += 256) {
        int e0  = ql * 4;                 // float offset within chunk
        int vl  = e0 / 81;                // voxel offset within chunk
        int j0  = e0 - vl * 81;
        int vox = vox0 + vl;
        int vx = vox / (V * V);
        int r  = vox - vx * (V * V);
        int vy = r / V;
        int vz = r - vy * V;
        int zn = vz + 1, yn = vy, xn = vx;
        if (zn == V) { zn = 0; yn = vy + 1; if (yn == V) { yn = 0; xn = vx + 1; } }
        float c0[3] = { (float)vx, (float)vy, (float)vz };
        float c1[3] = { (float)xn, (float)yn, (float)zn };
        float4 vv;
        float* vp = &vv.x;
        #pragma unroll
        for (int u = 0; u < 4; u++) {
            int jk = j0 + u;
            bool w = jk >= 81;
            int jj = w ? jk - 81 : jk;
            vp[u] = (w ? c1[s_sel[jj]] : c0[s_sel[jj]]) + s_add[jj];
        }
        ((float4*)s_buf)[ql] = vv;
    }
    __syncthreads();

    if (threadIdx.x == 0) {
        asm volatile("fence.proxy.async.shared::cta;" ::: "memory");
        uint32_t src = smem_u32(s_buf);
        #pragma unroll
        for (int b = 0; b < B; b++) {
            const float* dst = out + O_NBR + (size_t)b * PB_F + f0;
            asm volatile(
                "cp.async.bulk.global.shared::cta.bulk_group [%0], [%1], %2;"
                :: "l"(dst), "r"(src), "n"(CHUNK_BYTES) : "memory");
        }
        asm volatile("cp.async.bulk.commit_group;" ::: "memory");
        asm volatile("cp.async.bulk.wait_group 0;" ::: "memory");
    }
}

// ---------------------------------------------------------------------------
extern "C" void kernel_launch(void* const* d_in, const int* in_sizes, int n_in,
                              void* d_out, int out_size) {
    const float* pts = (const float*)d_in[0];
    float* out = (float*)d_out;

    static cudaStream_t s_side = nullptr;
    static cudaEvent_t ev_fork = nullptr, ev_join = nullptr;
    if (s_side == nullptr) {
        cudaStreamCreateWithFlags(&s_side, cudaStreamNonBlocking);
        cudaEventCreateWithFlags(&ev_fork, cudaEventDisableTiming);
        cudaEventCreateWithFlags(&ev_join, cudaEventDisableTiming);
    }

    // fork: neighbour table on side stream (TMA write-bound, low SM issue load)
    cudaEventRecord(ev_fork, 0);
    cudaStreamWaitEvent(s_side, ev_fork, 0);
    neighbour_kernel<<<NBR_BLOCKS, 256, 0, s_side>>>(out);
    cudaEventRecord(ev_join, s_side);

    // chain on legacy stream
    bin_kernel     <<<(B * N / 4 + 255) / 256, 256>>>(pts);
    scanA_kernel   <<<B * NTILES, 256>>>();
    scanB_kernel   <<<1, 256>>>();
    scanC_kernel   <<<B * NTILES, 256>>>();
    scatter_kernel <<<(B * N / 4 + 255) / 256, 256>>>();
    finalize_kernel<<<(B * NBINS + 255) / 256, 256>>>(out);

    cudaStreamWaitEvent(0, ev_join, 0);
}